// round 14
// baseline (speedup 1.0000x reference)
#include <cuda_runtime.h>
#include <cuda_bf16.h>
#include <cstdint>

#define NHEADS 12
#define HS     64
#define HID    768
#define OUTD   1536
#define NB     8
#define NL     512

// Packed-bf16 copies of the GEMM1 operands (built once per launch by k_cvt).
// g_xh[row][kp]  = (X[row, 2kp],  X[row, 2kp+1])   : [4096][384] uints
// g_wh[kp][n]    = (W[2kp, n],    W[2kp+1, n])     : [384][1536] uints
__device__ unsigned g_xh[NB * NL * (HID / 2)];
__device__ unsigned g_wh[(HID / 2) * OUTD];

// Rotated q/k scratch, packed bf16 pairs along d: [b, h, l, d/2].
__device__ unsigned g_qh[NB * NHEADS * NL * (HS / 2)];
__device__ unsigned g_kh[NB * NHEADS * NL * (HS / 2)];

__device__ __forceinline__ unsigned packbf(float lo, float hi) {
    __nv_bfloat162 v = __floats2bfloat162_rn(lo, hi);
    return *reinterpret_cast<unsigned*>(&v);
}

__device__ __forceinline__ void mma16(float c[4], const unsigned a[4], const unsigned b[2]) {
    asm volatile(
        "mma.sync.aligned.m16n8k16.row.col.f32.bf16.bf16.f32 "
        "{%0,%1,%2,%3}, {%4,%5,%6,%7}, {%8,%9}, {%0,%1,%2,%3};\n"
        : "+f"(c[0]), "+f"(c[1]), "+f"(c[2]), "+f"(c[3])
        : "r"(a[0]), "r"(a[1]), "r"(a[2]), "r"(a[3]), "r"(b[0]), "r"(b[1]));
}

__device__ __forceinline__ void ldmat4(unsigned a[4], const void* p) {
    unsigned sa = (unsigned)__cvta_generic_to_shared(p);
    asm volatile("ldmatrix.sync.aligned.m8n8.x4.shared.b16 {%0,%1,%2,%3}, [%4];"
                 : "=r"(a[0]), "=r"(a[1]), "=r"(a[2]), "=r"(a[3]) : "r"(sa));
}

__device__ __forceinline__ void cpasync16(void* s, const void* g) {
    unsigned sa = (unsigned)__cvta_generic_to_shared(s);
    asm volatile("cp.async.ca.shared.global [%0], [%1], 16;" :: "r"(sa), "l"(g));
}

// ---------------------------------------------------------------------------
// Kernel 0: convert X, W to packed bf16 (uint4-vectorized).
// ---------------------------------------------------------------------------
#define NX4 ((NB * NL * (HID / 2)) / 4)       // 393216 uint4 for X
#define NW4 (((HID / 2) * OUTD) / 4)          // 147456 uint4 for W

__global__ __launch_bounds__(256) void k_cvt(
    const float* __restrict__ X, const float* __restrict__ W)
{
    int j = blockIdx.x * 256 + threadIdx.x;
    if (j < NX4) {
        const float4 a = ((const float4*)X)[2 * j];
        const float4 b = ((const float4*)X)[2 * j + 1];
        ((uint4*)g_xh)[j] = make_uint4(packbf(a.x, a.y), packbf(a.z, a.w),
                                       packbf(b.x, b.y), packbf(b.z, b.w));
    } else if (j < NX4 + NW4) {
        int i  = j - NX4;
        int kp = i / (OUTD / 4);
        int c4 = i % (OUTD / 4);
        const float4 a = ((const float4*)W)[(size_t)(2 * kp) * (OUTD / 4) + c4];
        const float4 b = ((const float4*)W)[(size_t)(2 * kp + 1) * (OUTD / 4) + c4];
        ((uint4*)g_wh)[i] = make_uint4(packbf(a.x, b.x), packbf(a.y, b.y),
                                       packbf(a.z, b.z), packbf(a.w, b.w));
    }
}

// ---------------------------------------------------------------------------
// Kernel 1: x = X @ W + b, fused RoPE, scatter bf16 pairs to g_qh / g_kh.
// Pure-bf16 3-stage cp.async pipeline, K-step 64, 12 iterations.
// NOW 512 threads / 16 warps: warp grid 2(M) x 8(N), warp tile 64x16 ->
// 4 warps per SMSP for latency hiding; acc = 32 regs/thread.
// smem: As[3][128][36]u (ldmatrix-friendly), Bs[3][32][136]u (k-pair rows).
// ---------------------------------------------------------------------------
#define G1_ASTR  36
#define G1_BSTR  136
#define G1_ASZ   (128 * G1_ASTR)
#define G1_BSZ   (32 * G1_BSTR)
#define G1_SMEM  (3 * (G1_ASZ + G1_BSZ) * 4)

__global__ __launch_bounds__(512) void k_gemm1_rope(const float* __restrict__ bias)
{
    extern __shared__ unsigned sh[];
    unsigned* As = sh;                       // [3][128][36]
    unsigned* Bs = sh + 3 * G1_ASZ;          // [3][32][136]

    const int tid  = threadIdx.x;
    const int lane = tid & 31;
    const int warp = tid >> 5;               // 0..15
    const int wm   = warp >> 3;              // 0..1
    const int wn   = warp & 7;               // 0..7
    const int bm   = blockIdx.y;
    const int bn   = blockIdx.x;

    float acc[4][2][4];
    #pragma unroll
    for (int mi = 0; mi < 4; mi++)
        #pragma unroll
        for (int ni = 0; ni < 2; ni++)
            #pragma unroll
            for (int r = 0; r < 4; r++) acc[mi][ni][r] = 0.0f;

    auto loadStage = [&](int i, int s) {     // i = iteration (32 k-pairs each)
        unsigned* A = As + s * G1_ASZ;
        unsigned* B = Bs + s * G1_BSZ;
        const int ktp = i * 32;              // k-pair offset
        #pragma unroll
        for (int t = 0; t < 2; t++) {        // A: 1024 chunks, 2/thread
            int j = t * 512 + tid;
            int r = j >> 3, c = j & 7;
            cpasync16(&A[r * G1_ASTR + c * 4],
                      &g_xh[(size_t)(bm * 128 + r) * (HID / 2) + ktp + c * 4]);
        }
        #pragma unroll
        for (int t = 0; t < 2; t++) {        // B: 1024 chunks, 2/thread
            int j = t * 512 + tid;
            int r = j >> 5, c = j & 31;
            cpasync16(&B[r * G1_BSTR + c * 4],
                      &g_wh[(size_t)(ktp + r) * OUTD + bn * 128 + c * 4]);
        }
    };

    const int NK = HID / 64;   // 12
    #pragma unroll
    for (int s = 0; s < 2; s++) {
        loadStage(s, s);
        asm volatile("cp.async.commit_group;");
    }

    for (int i = 0; i < NK; i++) {
        asm volatile("cp.async.wait_group 1;");
        __syncthreads();
        if (i + 2 < NK) loadStage(i + 2, (i + 2) % 3);
        asm volatile("cp.async.commit_group;");

        const unsigned* A = As + (i % 3) * G1_ASZ;
        const unsigned* B = Bs + (i % 3) * G1_BSZ;

        #pragma unroll
        for (int kh = 0; kh < 4; kh++) {
            unsigned bfr[2][2];
            #pragma unroll
            for (int ni = 0; ni < 2; ni++) {
                int col = wn * 16 + ni * 8 + (lane >> 2);
                bfr[ni][0] = B[(kh * 8 + (lane & 3)) * G1_BSTR + col];
                bfr[ni][1] = B[(kh * 8 + (lane & 3) + 4) * G1_BSTR + col];
            }
            #pragma unroll
            for (int mi = 0; mi < 4; mi++) {
                unsigned afr[4];
                ldmat4(afr, &A[(wm * 64 + mi * 16 + (lane & 15)) * G1_ASTR
                               + kh * 8 + (lane >> 4) * 4]);
                #pragma unroll
                for (int ni = 0; ni < 2; ni++) mma16(acc[mi][ni], afr, bfr[ni]);
            }
        }
    }

    // Epilogue: bias + RoPE + scatter packed bf16.
    #pragma unroll
    for (int ni = 0; ni < 2; ni++) {
        int gc = bn * 128 + wn * 16 + ni * 8 + 2 * (lane & 3);  // even col
        int h  = gc >> 7;
        int s  = (gc >> 6) & 1;
        int d  = gc & 63;
        int pi = d >> 1;
        float inv = exp2f(-(float)pi * (13.287712379549449f / 32.0f));
        float bb0 = bias[gc], bb1 = bias[gc + 1];
        unsigned* dst = s ? g_kh : g_qh;
        #pragma unroll
        for (int mi = 0; mi < 4; mi++) {
            int gm0 = bm * 128 + wm * 64 + mi * 16 + (lane >> 2);
            #pragma unroll
            for (int half = 0; half < 2; half++) {
                int r  = gm0 + half * 8;
                int l  = r & (NL - 1);
                int bi = r >> 9;
                float ang = (float)l * inv;
                float sn = __sinf(ang), cs = __cosf(ang);
                float x1 = acc[mi][ni][half * 2 + 0] + bb0;
                float x2 = acc[mi][ni][half * 2 + 1] + bb1;
                dst[(((size_t)bi * NHEADS + h) * NL + l) * (HS / 2) + pi] =
                    packbf(x1 * cs - x2 * sn, x1 * sn + x2 * cs);
            }
        }
    }
}

// ---------------------------------------------------------------------------
// Kernel 2: logits[b,h,m,n] = (q . k) / 8, masked. ONE 128x128 tile per block.
// grid (nt=4, mt=4, z=96). mt > nt blocks: pure NEG fill (cheap, early-exit).
// Compute blocks: single-shot 36KB load -> one barrier -> MMA -> masked store.
// ---------------------------------------------------------------------------
#define A2_STR 36
#define A2_SZ  (128 * A2_STR)
#define A2_SMEM (2 * A2_SZ * 4)

__global__ __launch_bounds__(256) void k_attn(
    const int* __restrict__ am, float* __restrict__ out)
{
    extern __shared__ unsigned sh2[];
    unsigned* Qp = sh2;                       // [128][36]
    unsigned* Kp = sh2 + A2_SZ;               // [128][36]

    const int tid  = threadIdx.x;
    const int nt   = blockIdx.x;
    const int mt   = blockIdx.y;
    const int z    = blockIdx.z;              // b*12 + h
    const int m0   = mt * 128;
    const int n0   = nt * 128;
    const float NEG = -3.4028234663852886e38f;

    if (mt > nt) {
        const float4 negv = make_float4(NEG, NEG, NEG, NEG);
        #pragma unroll
        for (int it = 0; it < 16; it++) {
            int j = it * 256 + tid;
            int r = j >> 5;
            int c = j & 31;
            *(float4*)&out[((size_t)z * NL + m0 + r) * NL + n0 + c * 4] = negv;
        }
        return;
    }

    const int lane = tid & 31;
    const int warp = tid >> 5;
    const int wm   = warp >> 2;
    const int wn   = warp & 3;
    const int bi   = z / NHEADS;

    const int lr = tid >> 1;
    const int lc = (tid & 1) * 16;
    {
        const unsigned* qsrc = &g_qh[((size_t)z * NL + m0 + lr) * (HS / 2)];
        const unsigned* ksrc = &g_kh[((size_t)z * NL + n0 + lr) * (HS / 2)];
        #pragma unroll
        for (int c = 0; c < 4; c++) {
            cpasync16(&Qp[lr * A2_STR + lc + c * 4], qsrc + lc + c * 4);
            cpasync16(&Kp[lr * A2_STR + lc + c * 4], ksrc + lc + c * 4);
        }
    }
    asm volatile("cp.async.commit_group;");

    bool mok[4][2];
    #pragma unroll
    for (int mi = 0; mi < 4; mi++)
        #pragma unroll
        for (int half = 0; half < 2; half++)
            mok[mi][half] = am[bi * NL + m0 + wm * 64 + mi * 16 + (lane >> 2) + half * 8] != 0;
    bool nok[4][2];
    #pragma unroll
    for (int ni = 0; ni < 4; ni++) {
        int n = n0 + wn * 32 + ni * 8 + 2 * (lane & 3);
        nok[ni][0] = am[bi * NL + n] != 0;
        nok[ni][1] = am[bi * NL + n + 1] != 0;
    }

    float acc[4][4][4];
    #pragma unroll
    for (int mi = 0; mi < 4; mi++)
        #pragma unroll
        for (int ni = 0; ni < 4; ni++)
            #pragma unroll
            for (int r = 0; r < 4; r++) acc[mi][ni][r] = 0.0f;

    asm volatile("cp.async.wait_group 0;");
    __syncthreads();                          // the ONLY barrier

    #pragma unroll
    for (int kk8 = 0; kk8 < 4; kk8++) {
        int kidx = kk8 * 8 + (lane & 3);
        unsigned bfr[4][2];
        #pragma unroll
        for (int ni = 0; ni < 4; ni++) {
            int nrow = wn * 32 + ni * 8 + (lane >> 2);
            bfr[ni][0] = Kp[nrow * A2_STR + kidx];
            bfr[ni][1] = Kp[nrow * A2_STR + kidx + 4];
        }
        #pragma unroll
        for (int mi = 0; mi < 4; mi++) {
            unsigned afr[4];
            ldmat4(afr, &Qp[(wm * 64 + mi * 16 + (lane & 15)) * A2_STR
                            + kk8 * 8 + (lane >> 4) * 4]);
            #pragma unroll
            for (int ni = 0; ni < 4; ni++) mma16(acc[mi][ni], afr, bfr[ni]);
        }
    }

    #pragma unroll
    for (int mi = 0; mi < 4; mi++) {
        #pragma unroll
        for (int half = 0; half < 2; half++) {
            int gm = m0 + wm * 64 + mi * 16 + (lane >> 2) + half * 8;
            bool mo = mok[mi][half];
            #pragma unroll
            for (int ni = 0; ni < 4; ni++) {
                int gn = n0 + wn * 32 + ni * 8 + 2 * (lane & 3);
                float v0 = acc[mi][ni][half * 2 + 0] * 0.125f;
                float v1 = acc[mi][ni][half * 2 + 1] * 0.125f;
                float r0 = (mo && nok[ni][0] && gm <= gn)     ? v0 : NEG;
                float r1 = (mo && nok[ni][1] && gm <= gn + 1) ? v1 : NEG;
                *(float2*)&out[((size_t)z * NL + gm) * NL + gn] = make_float2(r0, r1);
            }
        }
    }
}

extern "C" void kernel_launch(void* const* d_in, const int* in_sizes, int n_in,
                              void* d_out, int out_size)
{
    const float* X    = (const float*)d_in[0];   // [8, 512, 768]
    const float* W    = (const float*)d_in[1];   // [768, 1536]
    const float* bias = (const float*)d_in[2];   // [1536]
    const int*   am   = (const int*)d_in[3];     // [8, 512]
    float* out        = (float*)d_out;           // [8, 12, 512, 512]

    (void)in_sizes; (void)n_in; (void)out_size;

    cudaFuncSetAttribute(k_gemm1_rope, cudaFuncAttributeMaxDynamicSharedMemorySize, G1_SMEM);
    cudaFuncSetAttribute(k_attn,       cudaFuncAttributeMaxDynamicSharedMemorySize, A2_SMEM);

    k_cvt<<<(NX4 + NW4 + 255) / 256, 256>>>(X, W);
    k_gemm1_rope<<<dim3(OUTD / 128, (NB * NL) / 128), 512, G1_SMEM>>>(bias);
    k_attn<<<dim3(4, 4, NB * NHEADS), 256, A2_SMEM>>>(am, out);
}

// round 15
// speedup vs baseline: 1.1058x; 1.1058x over previous
#include <cuda_runtime.h>
#include <cuda_bf16.h>
#include <cstdint>

#define NHEADS 12
#define HS     64
#define HID    768
#define OUTD   1536
#define NB     8
#define NL     512

// Packed-bf16 copies of the GEMM1 operands (built once per launch by k_cvt).
// g_xh[row][kp]  = (X[row, 2kp],  X[row, 2kp+1])   : [4096][384] uints
// g_wh[kp][n]    = (W[2kp, n],    W[2kp+1, n])     : [384][1536] uints
__device__ unsigned g_xh[NB * NL * (HID / 2)];
__device__ unsigned g_wh[(HID / 2) * OUTD];

// Rotated q/k scratch, packed bf16 pairs along d: [b, h, l, d/2].
__device__ unsigned g_qh[NB * NHEADS * NL * (HS / 2)];
__device__ unsigned g_kh[NB * NHEADS * NL * (HS / 2)];

__device__ __forceinline__ unsigned packbf(float lo, float hi) {
    __nv_bfloat162 v = __floats2bfloat162_rn(lo, hi);
    return *reinterpret_cast<unsigned*>(&v);
}

__device__ __forceinline__ void mma16(float c[4], const unsigned a[4], const unsigned b[2]) {
    asm volatile(
        "mma.sync.aligned.m16n8k16.row.col.f32.bf16.bf16.f32 "
        "{%0,%1,%2,%3}, {%4,%5,%6,%7}, {%8,%9}, {%0,%1,%2,%3};\n"
        : "+f"(c[0]), "+f"(c[1]), "+f"(c[2]), "+f"(c[3])
        : "r"(a[0]), "r"(a[1]), "r"(a[2]), "r"(a[3]), "r"(b[0]), "r"(b[1]));
}

__device__ __forceinline__ void ldmat4(unsigned a[4], const void* p) {
    unsigned sa = (unsigned)__cvta_generic_to_shared(p);
    asm volatile("ldmatrix.sync.aligned.m8n8.x4.shared.b16 {%0,%1,%2,%3}, [%4];"
                 : "=r"(a[0]), "=r"(a[1]), "=r"(a[2]), "=r"(a[3]) : "r"(sa));
}

__device__ __forceinline__ void cpasync16(void* s, const void* g) {
    unsigned sa = (unsigned)__cvta_generic_to_shared(s);
    asm volatile("cp.async.ca.shared.global [%0], [%1], 16;" :: "r"(sa), "l"(g));
}

// ---------------------------------------------------------------------------
// Kernel 0: convert X, W to packed bf16 (uint4-vectorized).
// ---------------------------------------------------------------------------
#define NX4 ((NB * NL * (HID / 2)) / 4)       // 393216 uint4 for X
#define NW4 (((HID / 2) * OUTD) / 4)          // 147456 uint4 for W

__global__ __launch_bounds__(256) void k_cvt(
    const float* __restrict__ X, const float* __restrict__ W)
{
    int j = blockIdx.x * 256 + threadIdx.x;
    if (j < NX4) {
        const float4 a = ((const float4*)X)[2 * j];
        const float4 b = ((const float4*)X)[2 * j + 1];
        ((uint4*)g_xh)[j] = make_uint4(packbf(a.x, a.y), packbf(a.z, a.w),
                                       packbf(b.x, b.y), packbf(b.z, b.w));
    } else if (j < NX4 + NW4) {
        int i  = j - NX4;
        int kp = i / (OUTD / 4);
        int c4 = i % (OUTD / 4);
        const float4 a = ((const float4*)W)[(size_t)(2 * kp) * (OUTD / 4) + c4];
        const float4 b = ((const float4*)W)[(size_t)(2 * kp + 1) * (OUTD / 4) + c4];
        ((uint4*)g_wh)[i] = make_uint4(packbf(a.x, b.x), packbf(a.y, b.y),
                                       packbf(a.z, b.z), packbf(a.w, b.w));
    }
}

// ---------------------------------------------------------------------------
// Kernel 1: x = X @ W + b, fused RoPE, scatter bf16 pairs to g_qh / g_kh.
// Pure-bf16 2-STAGE cp.async double buffer, K-step 64, 12 iterations.
// 8 warps 2(M)x4(N), warp 64x32 (R11 shape). smem 71.7KB -> 2 blocks/SM:
// two independent blocks overlap each other's barriers and load phases.
// smem: As[2][128][36]u (ldmatrix-friendly), Bs[2][32][136]u (k-pair rows).
// ---------------------------------------------------------------------------
#define G1_ASTR  36
#define G1_BSTR  136
#define G1_ASZ   (128 * G1_ASTR)
#define G1_BSZ   (32 * G1_BSTR)
#define G1_SMEM  (2 * (G1_ASZ + G1_BSZ) * 4)

__global__ __launch_bounds__(256, 2) void k_gemm1_rope(const float* __restrict__ bias)
{
    extern __shared__ unsigned sh[];
    unsigned* As = sh;                       // [2][128][36]
    unsigned* Bs = sh + 2 * G1_ASZ;          // [2][32][136]

    const int tid  = threadIdx.x;
    const int lane = tid & 31;
    const int warp = tid >> 5;
    const int wm   = warp >> 2;
    const int wn   = warp & 3;
    const int bm   = blockIdx.y;
    const int bn   = blockIdx.x;

    float acc[4][4][4];
    #pragma unroll
    for (int mi = 0; mi < 4; mi++)
        #pragma unroll
        for (int ni = 0; ni < 4; ni++)
            #pragma unroll
            for (int r = 0; r < 4; r++) acc[mi][ni][r] = 0.0f;

    auto loadStage = [&](int i, int s) {     // i = iteration (32 k-pairs each)
        unsigned* A = As + s * G1_ASZ;
        unsigned* B = Bs + s * G1_BSZ;
        const int ktp = i * 32;              // k-pair offset
        #pragma unroll
        for (int t = 0; t < 4; t++) {        // A: 1024 chunks, 4/thread
            int j = t * 256 + tid;
            int r = j >> 3, c = j & 7;
            cpasync16(&A[r * G1_ASTR + c * 4],
                      &g_xh[(size_t)(bm * 128 + r) * (HID / 2) + ktp + c * 4]);
        }
        #pragma unroll
        for (int t = 0; t < 4; t++) {        // B: 1024 chunks, 4/thread
            int j = t * 256 + tid;
            int r = j >> 5, c = j & 31;
            cpasync16(&B[r * G1_BSTR + c * 4],
                      &g_wh[(size_t)(ktp + r) * OUTD + bn * 128 + c * 4]);
        }
    };

    const int NK = HID / 64;   // 12
    loadStage(0, 0);
    asm volatile("cp.async.commit_group;");

    for (int i = 0; i < NK; i++) {
        asm volatile("cp.async.wait_group 0;");   // stage i resident
        __syncthreads();                          // all warps done with stage i-1
        if (i + 1 < NK) loadStage(i + 1, (i + 1) & 1);
        asm volatile("cp.async.commit_group;");

        const unsigned* A = As + (i & 1) * G1_ASZ;
        const unsigned* B = Bs + (i & 1) * G1_BSZ;

        #pragma unroll
        for (int kh = 0; kh < 4; kh++) {
            unsigned bfr[4][2];
            #pragma unroll
            for (int ni = 0; ni < 4; ni++) {
                int col = wn * 32 + ni * 8 + (lane >> 2);
                bfr[ni][0] = B[(kh * 8 + (lane & 3)) * G1_BSTR + col];
                bfr[ni][1] = B[(kh * 8 + (lane & 3) + 4) * G1_BSTR + col];
            }
            #pragma unroll
            for (int mi = 0; mi < 4; mi++) {
                unsigned afr[4];
                ldmat4(afr, &A[(wm * 64 + mi * 16 + (lane & 15)) * G1_ASTR
                               + kh * 8 + (lane >> 4) * 4]);
                #pragma unroll
                for (int ni = 0; ni < 4; ni++) mma16(acc[mi][ni], afr, bfr[ni]);
            }
        }
    }

    // Epilogue: bias + RoPE + scatter packed bf16.
    #pragma unroll
    for (int ni = 0; ni < 4; ni++) {
        int gc = bn * 128 + wn * 32 + ni * 8 + 2 * (lane & 3);  // even col
        int h  = gc >> 7;
        int s  = (gc >> 6) & 1;
        int d  = gc & 63;
        int pi = d >> 1;
        float inv = exp2f(-(float)pi * (13.287712379549449f / 32.0f));
        float bb0 = bias[gc], bb1 = bias[gc + 1];
        unsigned* dst = s ? g_kh : g_qh;
        #pragma unroll
        for (int mi = 0; mi < 4; mi++) {
            int gm0 = bm * 128 + wm * 64 + mi * 16 + (lane >> 2);
            #pragma unroll
            for (int half = 0; half < 2; half++) {
                int r  = gm0 + half * 8;
                int l  = r & (NL - 1);
                int bi = r >> 9;
                float ang = (float)l * inv;
                float sn = __sinf(ang), cs = __cosf(ang);
                float x1 = acc[mi][ni][half * 2 + 0] + bb0;
                float x2 = acc[mi][ni][half * 2 + 1] + bb1;
                dst[(((size_t)bi * NHEADS + h) * NL + l) * (HS / 2) + pi] =
                    packbf(x1 * cs - x2 * sn, x1 * sn + x2 * cs);
            }
        }
    }
}

// ---------------------------------------------------------------------------
// Kernel 2: logits[b,h,m,n] = (q . k) / 8, masked. ONE 128x128 tile per block.
// grid (nt=4, mt=4, z=96). mt > nt blocks: pure NEG fill (cheap, early-exit).
// Compute blocks: single-shot 36KB load -> one barrier -> MMA -> masked store.
// ---------------------------------------------------------------------------
#define A2_STR 36
#define A2_SZ  (128 * A2_STR)
#define A2_SMEM (2 * A2_SZ * 4)

__global__ __launch_bounds__(256) void k_attn(
    const int* __restrict__ am, float* __restrict__ out)
{
    extern __shared__ unsigned sh2[];
    unsigned* Qp = sh2;                       // [128][36]
    unsigned* Kp = sh2 + A2_SZ;               // [128][36]

    const int tid  = threadIdx.x;
    const int nt   = blockIdx.x;
    const int mt   = blockIdx.y;
    const int z    = blockIdx.z;              // b*12 + h
    const int m0   = mt * 128;
    const int n0   = nt * 128;
    const float NEG = -3.4028234663852886e38f;

    if (mt > nt) {
        const float4 negv = make_float4(NEG, NEG, NEG, NEG);
        #pragma unroll
        for (int it = 0; it < 16; it++) {
            int j = it * 256 + tid;
            int r = j >> 5;
            int c = j & 31;
            *(float4*)&out[((size_t)z * NL + m0 + r) * NL + n0 + c * 4] = negv;
        }
        return;
    }

    const int lane = tid & 31;
    const int warp = tid >> 5;
    const int wm   = warp >> 2;
    const int wn   = warp & 3;
    const int bi   = z / NHEADS;

    const int lr = tid >> 1;
    const int lc = (tid & 1) * 16;
    {
        const unsigned* qsrc = &g_qh[((size_t)z * NL + m0 + lr) * (HS / 2)];
        const unsigned* ksrc = &g_kh[((size_t)z * NL + n0 + lr) * (HS / 2)];
        #pragma unroll
        for (int c = 0; c < 4; c++) {
            cpasync16(&Qp[lr * A2_STR + lc + c * 4], qsrc + lc + c * 4);
            cpasync16(&Kp[lr * A2_STR + lc + c * 4], ksrc + lc + c * 4);
        }
    }
    asm volatile("cp.async.commit_group;");

    bool mok[4][2];
    #pragma unroll
    for (int mi = 0; mi < 4; mi++)
        #pragma unroll
        for (int half = 0; half < 2; half++)
            mok[mi][half] = am[bi * NL + m0 + wm * 64 + mi * 16 + (lane >> 2) + half * 8] != 0;
    bool nok[4][2];
    #pragma unroll
    for (int ni = 0; ni < 4; ni++) {
        int n = n0 + wn * 32 + ni * 8 + 2 * (lane & 3);
        nok[ni][0] = am[bi * NL + n] != 0;
        nok[ni][1] = am[bi * NL + n + 1] != 0;
    }

    float acc[4][4][4];
    #pragma unroll
    for (int mi = 0; mi < 4; mi++)
        #pragma unroll
        for (int ni = 0; ni < 4; ni++)
            #pragma unroll
            for (int r = 0; r < 4; r++) acc[mi][ni][r] = 0.0f;

    asm volatile("cp.async.wait_group 0;");
    __syncthreads();                          // the ONLY barrier

    #pragma unroll
    for (int kk8 = 0; kk8 < 4; kk8++) {
        int kidx = kk8 * 8 + (lane & 3);
        unsigned bfr[4][2];
        #pragma unroll
        for (int ni = 0; ni < 4; ni++) {
            int nrow = wn * 32 + ni * 8 + (lane >> 2);
            bfr[ni][0] = Kp[nrow * A2_STR + kidx];
            bfr[ni][1] = Kp[nrow * A2_STR + kidx + 4];
        }
        #pragma unroll
        for (int mi = 0; mi < 4; mi++) {
            unsigned afr[4];
            ldmat4(afr, &Qp[(wm * 64 + mi * 16 + (lane & 15)) * A2_STR
                            + kk8 * 8 + (lane >> 4) * 4]);
            #pragma unroll
            for (int ni = 0; ni < 4; ni++) mma16(acc[mi][ni], afr, bfr[ni]);
        }
    }

    #pragma unroll
    for (int mi = 0; mi < 4; mi++) {
        #pragma unroll
        for (int half = 0; half < 2; half++) {
            int gm = m0 + wm * 64 + mi * 16 + (lane >> 2) + half * 8;
            bool mo = mok[mi][half];
            #pragma unroll
            for (int ni = 0; ni < 4; ni++) {
                int gn = n0 + wn * 32 + ni * 8 + 2 * (lane & 3);
                float v0 = acc[mi][ni][half * 2 + 0] * 0.125f;
                float v1 = acc[mi][ni][half * 2 + 1] * 0.125f;
                float r0 = (mo && nok[ni][0] && gm <= gn)     ? v0 : NEG;
                float r1 = (mo && nok[ni][1] && gm <= gn + 1) ? v1 : NEG;
                *(float2*)&out[((size_t)z * NL + gm) * NL + gn] = make_float2(r0, r1);
            }
        }
    }
}

extern "C" void kernel_launch(void* const* d_in, const int* in_sizes, int n_in,
                              void* d_out, int out_size)
{
    const float* X    = (const float*)d_in[0];   // [8, 512, 768]
    const float* W    = (const float*)d_in[1];   // [768, 1536]
    const float* bias = (const float*)d_in[2];   // [1536]
    const int*   am   = (const int*)d_in[3];     // [8, 512]
    float* out        = (float*)d_out;           // [8, 12, 512, 512]

    (void)in_sizes; (void)n_in; (void)out_size;

    cudaFuncSetAttribute(k_gemm1_rope, cudaFuncAttributeMaxDynamicSharedMemorySize, G1_SMEM);
    cudaFuncSetAttribute(k_attn,       cudaFuncAttributeMaxDynamicSharedMemorySize, A2_SMEM);

    k_cvt<<<(NX4 + NW4 + 255) / 256, 256>>>(X, W);
    k_gemm1_rope<<<dim3(OUTD / 128, (NB * NL) / 128), 256, G1_SMEM>>>(bias);
    k_attn<<<dim3(4, 4, NB * NHEADS), 256, A2_SMEM>>>(am, out);
}